// round 3
// baseline (speedup 1.0000x reference)
#include <cuda_runtime.h>
#include <cuda_bf16.h>
#include <math.h>
#include <float.h>

#define NN 100000
#define EE 1600000
#define FIN 256
#define HD 64
#define CD 40

// scratch (static device arrays are allowed; 16B-aligned for float4 paths)
__device__ __align__(16) float g_deg[NN];
__device__ __align__(16) float g_norm[EE];
__device__ __align__(16) float g_H1[NN * HD];
__device__ __align__(16) float g_A1[NN * HD];
__device__ __align__(16) float g_H2[NN * CD];
__device__ __align__(16) float g_A2[NN * CD];
__device__ int g_src[EE];
__device__ int g_dst[EE];
__device__ int g_is64;

// ---------- dtype detection: int64 vs int32 edge_index ----------------------
__global__ void k_detect(const void* __restrict__ ei) {
    if (threadIdx.x == 0 && blockIdx.x == 0) {
        const long long* p = (const long long*)ei;
        int ok = 1;
        for (int i = 0; i < 2048; i++) {
            long long v = p[i];
            if (v < 0 || v >= NN) { ok = 0; break; }
        }
        g_is64 = ok;
    }
}

// ---------- extract indices to int32 ----------------------------------------
__global__ void k_extract(const void* __restrict__ ei) {
    int e = blockIdx.x * blockDim.x + threadIdx.x;
    if (e >= EE) return;
    int s, d;
    if (g_is64) {
        const long long* p = (const long long*)ei;
        s = (int)p[e];
        d = (int)p[EE + e];
    } else {
        const int* p = (const int*)ei;
        s = p[e];
        d = p[EE + e];
    }
    g_src[e] = s;
    g_dst[e] = d;
}

// ---------- init: zero accumulators, deg = 1 (self loop) --------------------
__global__ void k_init() {
    int idx = blockIdx.x * blockDim.x + threadIdx.x;
    if (idx < NN * HD) g_A1[idx] = 0.f;
    if (idx < NN * CD) g_A2[idx] = 0.f;
    if (idx < NN)      g_deg[idx] = 1.0f;
}

// ---------- degree accumulation ---------------------------------------------
__global__ void k_deg(const float* __restrict__ w) {
    int e = blockIdx.x * blockDim.x + threadIdx.x;
    if (e < EE) atomicAdd(&g_deg[g_dst[e]], w[e]);
}

// ---------- deg -> dinv in place --------------------------------------------
__global__ void k_dinv() {
    int i = blockIdx.x * blockDim.x + threadIdx.x;
    if (i < NN) {
        float d = g_deg[i];
        g_deg[i] = (d > 0.f) ? rsqrtf(d) : 0.f;
    }
}

// ---------- per-edge norm ----------------------------------------------------
__global__ void k_norm(const float* __restrict__ w) {
    int e = blockIdx.x * blockDim.x + threadIdx.x;
    if (e < EE) g_norm[e] = g_deg[g_src[e]] * w[e] * g_deg[g_dst[e]];
}

// ---------- GEMM1: H1 = x @ W1  (100000x256 @ 256x64) -----------------------
__global__ void k_gemm1(const float* __restrict__ x, const float* __restrict__ W1) {
    __shared__ float sW[64 * 64];
    __shared__ float sxT[64 * 68];

    int tid = threadIdx.x;
    int rowbase = blockIdx.x * 64;
    int jq = tid & 15;
    int rq = tid >> 4;

    float4 acc0 = {0,0,0,0}, acc1 = {0,0,0,0}, acc2 = {0,0,0,0}, acc3 = {0,0,0,0};

    for (int kc = 0; kc < 4; kc++) {
        __syncthreads();
        #pragma unroll
        for (int idx = tid; idx < 4096; idx += 256)
            sW[idx] = W1[kc * 4096 + idx];
        #pragma unroll
        for (int idx = tid; idx < 4096; idx += 256) {
            int k = idx & 63, r = idx >> 6;
            int row = rowbase + r;
            float v = (row < NN) ? x[row * FIN + kc * 64 + k] : 0.f;
            sxT[k * 68 + r] = v;
        }
        __syncthreads();
        #pragma unroll
        for (int k = 0; k < 64; k++) {
            float4 xv = *(const float4*)&sxT[k * 68 + rq * 4];
            float4 wv = *(const float4*)&sW[k * 64 + jq * 4];
            acc0.x += xv.x * wv.x; acc0.y += xv.x * wv.y; acc0.z += xv.x * wv.z; acc0.w += xv.x * wv.w;
            acc1.x += xv.y * wv.x; acc1.y += xv.y * wv.y; acc1.z += xv.y * wv.z; acc1.w += xv.y * wv.w;
            acc2.x += xv.z * wv.x; acc2.y += xv.z * wv.y; acc2.z += xv.z * wv.z; acc2.w += xv.z * wv.w;
            acc3.x += xv.w * wv.x; acc3.y += xv.w * wv.y; acc3.z += xv.w * wv.z; acc3.w += xv.w * wv.w;
        }
    }
    int r0 = rowbase + rq * 4;
    if (r0 + 0 < NN) *(float4*)&g_H1[(r0 + 0) * HD + jq * 4] = acc0;
    if (r0 + 1 < NN) *(float4*)&g_H1[(r0 + 1) * HD + jq * 4] = acc1;
    if (r0 + 2 < NN) *(float4*)&g_H1[(r0 + 2) * HD + jq * 4] = acc2;
    if (r0 + 3 < NN) *(float4*)&g_H1[(r0 + 3) * HD + jq * 4] = acc3;
}

// ---------- edge aggregation L1: A1[dst] += H1[src]*norm --------------------
__global__ void k_agg1() {
    long long idx = (long long)blockIdx.x * blockDim.x + threadIdx.x;
    if (idx >= (long long)EE * 16) return;
    int e  = (int)(idx >> 4);
    int c4 = ((int)idx & 15) * 4;
    int src = g_src[e];
    int dst = g_dst[e];
    float nrm = g_norm[e];
    float4 h = *(const float4*)&g_H1[src * HD + c4];
    float* out = &g_A1[dst * HD + c4];
    atomicAdd(out + 0, h.x * nrm);
    atomicAdd(out + 1, h.y * nrm);
    atomicAdd(out + 2, h.z * nrm);
    atomicAdd(out + 3, h.w * nrm);
}

// ---------- post1: H1 = relu(A1 + H1*dinv^2 + b1) ---------------------------
__global__ void k_post1(const float* __restrict__ b1) {
    int idx = blockIdx.x * blockDim.x + threadIdx.x;
    if (idx < NN * HD) {
        int row = idx >> 6;
        float di = g_deg[row];
        float v = g_A1[idx] + g_H1[idx] * di * di + b1[idx & 63];
        g_H1[idx] = fmaxf(v, 0.f);
    }
}

// ---------- GEMM2: H2 = H1 @ W2  (100000x64 @ 64x40) ------------------------
__global__ void k_gemm2(const float* __restrict__ W2) {
    __shared__ float sW2[64 * 40];
    __shared__ float sx[32 * 64];

    int tid = threadIdx.x;
    int rowbase = blockIdx.x * 32;

    for (int idx = tid; idx < 64 * 40; idx += 320)
        sW2[idx] = W2[idx];
    for (int idx = tid; idx < 32 * 64; idx += 320) {
        int r = idx >> 6, k = idx & 63;
        int row = rowbase + r;
        sx[idx] = (row < NN) ? g_H1[row * HD + k] : 0.f;
    }
    __syncthreads();

    int j  = tid % 40;
    int rg = tid / 40;
    float a0 = 0.f, a1 = 0.f, a2 = 0.f, a3 = 0.f;
    #pragma unroll
    for (int k = 0; k < 64; k++) {
        float w = sW2[k * 40 + j];
        a0 += sx[(rg * 4 + 0) * 64 + k] * w;
        a1 += sx[(rg * 4 + 1) * 64 + k] * w;
        a2 += sx[(rg * 4 + 2) * 64 + k] * w;
        a3 += sx[(rg * 4 + 3) * 64 + k] * w;
    }
    int r0 = rowbase + rg * 4;
    if (r0 + 0 < NN) g_H2[(r0 + 0) * CD + j] = a0;
    if (r0 + 1 < NN) g_H2[(r0 + 1) * CD + j] = a1;
    if (r0 + 2 < NN) g_H2[(r0 + 2) * CD + j] = a2;
    if (r0 + 3 < NN) g_H2[(r0 + 3) * CD + j] = a3;
}

// ---------- edge aggregation L2: A2[dst] += H2[src]*norm --------------------
__global__ void k_agg2() {
    long long idx = (long long)blockIdx.x * blockDim.x + threadIdx.x;
    if (idx >= (long long)EE * 10) return;
    int e  = (int)(idx / 10);
    int c4 = ((int)(idx % 10)) * 4;
    int src = g_src[e];
    int dst = g_dst[e];
    float nrm = g_norm[e];
    float4 h = *(const float4*)&g_H2[src * CD + c4];
    float* out = &g_A2[dst * CD + c4];
    atomicAdd(out + 0, h.x * nrm);
    atomicAdd(out + 1, h.y * nrm);
    atomicAdd(out + 2, h.z * nrm);
    atomicAdd(out + 3, h.w * nrm);
}

// ---------- final: v = A2 + H2*dinv^2 + b2; log_softmax ---------------------
__global__ void k_final(const float* __restrict__ b2, float* __restrict__ out) {
    int warp = threadIdx.x >> 5;
    int row  = blockIdx.x * 8 + warp;
    int lane = threadIdx.x & 31;
    if (row >= NN) return;

    float di = g_deg[row];
    float sn = di * di;
    int base = row * CD;

    float a0 = g_A2[base + lane] + g_H2[base + lane] * sn + b2[lane];
    float a1 = -FLT_MAX;
    if (lane < 8) {
        int c = lane + 32;
        a1 = g_A2[base + c] + g_H2[base + c] * sn + b2[c];
    }
    float m = fmaxf(a0, a1);
    #pragma unroll
    for (int off = 16; off; off >>= 1)
        m = fmaxf(m, __shfl_xor_sync(0xFFFFFFFFu, m, off));
    float s = __expf(a0 - m) + ((lane < 8) ? __expf(a1 - m) : 0.f);
    #pragma unroll
    for (int off = 16; off; off >>= 1)
        s += __shfl_xor_sync(0xFFFFFFFFu, s, off);
    float ls = __logf(s);
    out[base + lane] = a0 - m - ls;
    if (lane < 8) out[base + lane + 32] = a1 - m - ls;
}

extern "C" void kernel_launch(void* const* d_in, const int* in_sizes, int n_in,
                              void* d_out, int out_size) {
    const float* x   = (const float*)d_in[0];
    const void*  ei  = d_in[1];
    const float* ea  = (const float*)d_in[2];
    const float* W1  = (const float*)d_in[3];
    const float* b1  = (const float*)d_in[4];
    const float* W2  = (const float*)d_in[5];
    const float* b2  = (const float*)d_in[6];
    float*       out = (float*)d_out;

    k_detect <<<1, 32>>>(ei);
    k_extract<<<(EE + 255) / 256, 256>>>(ei);
    k_init   <<<(NN * HD + 255) / 256, 256>>>();
    k_deg    <<<(EE + 255) / 256, 256>>>(ea);
    k_dinv   <<<(NN + 255) / 256, 256>>>();
    k_norm   <<<(EE + 255) / 256, 256>>>(ea);
    k_gemm1  <<<(NN + 63) / 64, 256>>>(x, W1);
    k_agg1   <<<(EE * 16 + 255) / 256, 256>>>();
    k_post1  <<<(NN * HD + 255) / 256, 256>>>(b1);
    k_gemm2  <<<(NN + 31) / 32, 320>>>(W2);
    k_agg2   <<<((long long)EE * 10 + 255) / 256, 256>>>();
    k_final  <<<(NN + 7) / 8, 256>>>(b2, out);
}

// round 8
// speedup vs baseline: 1.5321x; 1.5321x over previous
#include <cuda_runtime.h>
#include <cuda_bf16.h>
#include <math.h>
#include <float.h>

#define NN 100000
#define EE 1600000
#define FIN 256
#define HD 64
#define CD 40
#define NB 98          // ceil(NN/1024) scan blocks

// ---- scratch (static device arrays allowed) --------------------------------
__device__ __align__(16) float g_deg[NN];
__device__ __align__(16) float g_norm[EE];
__device__ __align__(16) float g_H1[NN * HD];    // x@W1 (raw)
__device__ __align__(16) float g_H1b[NN * HD];   // relu(agg1)
__device__ __align__(16) float g_H2[NN * CD];    // h1b@W2 (raw)
__device__ int g_src[EE];
__device__ int g_dst[EE];
__device__ int g_cnt[NN];
__device__ int g_cur[NN];
__device__ int g_rowptr[NN + 1];
__device__ int g_bsum[128];
__device__ int g_csr[EE];
__device__ int g_is64;

// ---------- dtype detection (parallel, 1 block) -----------------------------
__global__ void k_detect(const void* __restrict__ ei) {
    const long long* p = (const long long*)ei;
    int t = threadIdx.x;
    int bad = 0;
    #pragma unroll
    for (int i = 0; i < 8; i++) {
        long long v = p[t * 8 + i];
        if (v < 0 || v >= NN) bad = 1;
    }
    __shared__ int s_bad;
    if (t == 0) s_bad = 0;
    __syncthreads();
    if (__syncthreads_or(bad)) { if (t == 0) g_is64 = 0; }
    else                       { if (t == 0) g_is64 = 1; }
}

// ---------- extract indices to int32 ----------------------------------------
__global__ void k_extract(const void* __restrict__ ei) {
    int e = blockIdx.x * blockDim.x + threadIdx.x;
    if (e >= EE) return;
    int s, d;
    if (g_is64) {
        const long long* p = (const long long*)ei;
        s = (int)p[e]; d = (int)p[EE + e];
    } else {
        const int* p = (const int*)ei;
        s = p[e]; d = p[EE + e];
    }
    g_src[e] = s; g_dst[e] = d;
}

// ---------- init ------------------------------------------------------------
__global__ void k_init() {
    int i = blockIdx.x * blockDim.x + threadIdx.x;
    if (i < NN) { g_deg[i] = 1.0f; g_cnt[i] = 0; g_cur[i] = 0; }
}

// ---------- count + weighted degree -----------------------------------------
__global__ void k_count(const float* __restrict__ w) {
    int e = blockIdx.x * blockDim.x + threadIdx.x;
    if (e < EE) {
        int d = g_dst[e];
        atomicAdd(&g_cnt[d], 1);
        atomicAdd(&g_deg[d], w[e]);
    }
}

// ---------- deg -> dinv ------------------------------------------------------
__global__ void k_dinv() {
    int i = blockIdx.x * blockDim.x + threadIdx.x;
    if (i < NN) {
        float d = g_deg[i];
        g_deg[i] = (d > 0.f) ? rsqrtf(d) : 0.f;
    }
}

// ---------- per-edge norm ----------------------------------------------------
__global__ void k_norm(const float* __restrict__ w) {
    int e = blockIdx.x * blockDim.x + threadIdx.x;
    if (e < EE) g_norm[e] = g_deg[g_src[e]] * w[e] * g_deg[g_dst[e]];
}

// ---------- scan (3 kernels): rowptr = exclusive scan of cnt -----------------
__global__ void k_scan1() {
    __shared__ int s[1024];
    int b = blockIdx.x, t = threadIdx.x;
    int i = b * 1024 + t;
    int v = (i < NN) ? g_cnt[i] : 0;
    s[t] = v; __syncthreads();
    for (int off = 1; off < 1024; off <<= 1) {
        int add = (t >= off) ? s[t - off] : 0;
        __syncthreads();
        s[t] += add;
        __syncthreads();
    }
    if (i < NN) g_rowptr[i + 1] = s[t];
    if (t == 1023) g_bsum[b] = s[t];
}
__global__ void k_scan2() {
    __shared__ int s[128];
    int t = threadIdx.x;
    int v = (t < NB) ? g_bsum[t] : 0;
    s[t] = v; __syncthreads();
    for (int off = 1; off < 128; off <<= 1) {
        int add = (t >= off) ? s[t - off] : 0;
        __syncthreads();
        s[t] += add;
        __syncthreads();
    }
    if (t < NB) g_bsum[t] = s[t];
}
__global__ void k_scan3() {
    int b = blockIdx.x, t = threadIdx.x;
    int i = b * 1024 + t;
    if (b > 0 && i < NN) g_rowptr[i + 1] += g_bsum[b - 1];
    if (b == 0 && t == 0) g_rowptr[0] = 0;
}

// ---------- fill CSR ---------------------------------------------------------
__global__ void k_fill() {
    int e = blockIdx.x * blockDim.x + threadIdx.x;
    if (e < EE) {
        int d = g_dst[e];
        int p = atomicAdd(&g_cur[d], 1);
        g_csr[g_rowptr[d] + p] = e;
    }
}

// ---------- GEMM1: H1 = x @ W1  (256-row tile, 8x8 reg blocking) -------------
__global__ void k_gemm1(const float* __restrict__ x, const float* __restrict__ W1) {
    __shared__ float sW[16 * 64];     // [k][n]
    __shared__ float sxT[16 * 264];   // [k][r], padded

    int tid = threadIdx.x;
    int rowbase = blockIdx.x * 256;
    int tx = tid & 7;       // col group: cols 8*tx..8*tx+7
    int ty = tid >> 3;      // row group: rows 8*ty..8*ty+7 (0..31)

    float acc[8][8];
    #pragma unroll
    for (int i = 0; i < 8; i++)
        #pragma unroll
        for (int j = 0; j < 8; j++) acc[i][j] = 0.f;

    for (int kc = 0; kc < 16; kc++) {
        __syncthreads();
        #pragma unroll
        for (int i = tid; i < 1024; i += 256)
            sW[i] = W1[(kc * 16 + (i >> 6)) * 64 + (i & 63)];
        #pragma unroll
        for (int i = tid; i < 1024; i += 256) {
            int r = i >> 2, kq = (i & 3) * 4;
            int row = rowbase + r;
            float4 v = (row < NN) ? *(const float4*)&x[row * FIN + kc * 16 + kq]
                                  : make_float4(0.f, 0.f, 0.f, 0.f);
            sxT[(kq + 0) * 264 + r] = v.x;
            sxT[(kq + 1) * 264 + r] = v.y;
            sxT[(kq + 2) * 264 + r] = v.z;
            sxT[(kq + 3) * 264 + r] = v.w;
        }
        __syncthreads();
        #pragma unroll
        for (int k = 0; k < 16; k++) {
            float xr[8], wn[8];
            *(float4*)&xr[0] = *(const float4*)&sxT[k * 264 + ty * 8];
            *(float4*)&xr[4] = *(const float4*)&sxT[k * 264 + ty * 8 + 4];
            *(float4*)&wn[0] = *(const float4*)&sW[k * 64 + tx * 8];
            *(float4*)&wn[4] = *(const float4*)&sW[k * 64 + tx * 8 + 4];
            #pragma unroll
            for (int i = 0; i < 8; i++)
                #pragma unroll
                for (int j = 0; j < 8; j++)
                    acc[i][j] += xr[i] * wn[j];
        }
    }
    #pragma unroll
    for (int i = 0; i < 8; i++) {
        int row = rowbase + ty * 8 + i;
        if (row < NN) {
            *(float4*)&g_H1[row * HD + tx * 8]     = make_float4(acc[i][0], acc[i][1], acc[i][2], acc[i][3]);
            *(float4*)&g_H1[row * HD + tx * 8 + 4] = make_float4(acc[i][4], acc[i][5], acc[i][6], acc[i][7]);
        }
    }
}

// ---------- agg1 (CSR gather) + self + bias + relu, fused --------------------
// 16 threads per node; each handles 4 features.
__global__ void k_agg1(const float* __restrict__ b1) {
    int tid = threadIdx.x;
    int v  = blockIdx.x * 16 + (tid >> 4);
    if (v >= NN) return;
    int c4 = (tid & 15) * 4;

    int e   = g_rowptr[v];
    int end = g_rowptr[v + 1];
    float4 acc = make_float4(0.f, 0.f, 0.f, 0.f);

    int src = 0; float nrm = 0.f;
    if (e < end) {
        int eid = g_csr[e];
        src = g_src[eid]; nrm = g_norm[eid];
    }
    while (e < end) {
        int src_c = src; float nrm_c = nrm;
        int e2 = e + 1;
        if (e2 < end) {
            int eid2 = g_csr[e2];
            src = g_src[eid2]; nrm = g_norm[eid2];
        }
        float4 h = *(const float4*)&g_H1[src_c * HD + c4];
        acc.x += h.x * nrm_c; acc.y += h.y * nrm_c;
        acc.z += h.z * nrm_c; acc.w += h.w * nrm_c;
        e = e2;
    }

    float di = g_deg[v];
    float sn = di * di;
    float4 hs = *(const float4*)&g_H1[v * HD + c4];
    float4 bb = *(const float4*)&b1[c4];
    float4 o;
    o.x = fmaxf(acc.x + hs.x * sn + bb.x, 0.f);
    o.y = fmaxf(acc.y + hs.y * sn + bb.y, 0.f);
    o.z = fmaxf(acc.z + hs.z * sn + bb.z, 0.f);
    o.w = fmaxf(acc.w + hs.w * sn + bb.w, 0.f);
    *(float4*)&g_H1b[v * HD + c4] = o;
}

// ---------- GEMM2: H2 = H1b @ W2  (100000x64 @ 64x40) ------------------------
__global__ void k_gemm2(const float* __restrict__ W2) {
    __shared__ float sW2[64 * 40];
    __shared__ float sx[32 * 64];

    int tid = threadIdx.x;
    int rowbase = blockIdx.x * 32;

    for (int idx = tid; idx < 64 * 40; idx += 320)
        sW2[idx] = W2[idx];
    for (int idx = tid; idx < 32 * 64; idx += 320) {
        int r = idx >> 6, k = idx & 63;
        int row = rowbase + r;
        sx[idx] = (row < NN) ? g_H1b[row * HD + k] : 0.f;
    }
    __syncthreads();

    int j  = tid % 40;
    int rg = tid / 40;
    float a0 = 0.f, a1 = 0.f, a2 = 0.f, a3 = 0.f;
    #pragma unroll
    for (int k = 0; k < 64; k++) {
        float w = sW2[k * 40 + j];
        a0 += sx[(rg * 4 + 0) * 64 + k] * w;
        a1 += sx[(rg * 4 + 1) * 64 + k] * w;
        a2 += sx[(rg * 4 + 2) * 64 + k] * w;
        a3 += sx[(rg * 4 + 3) * 64 + k] * w;
    }
    int r0 = rowbase + rg * 4;
    if (r0 + 0 < NN) g_H2[(r0 + 0) * CD + j] = a0;
    if (r0 + 1 < NN) g_H2[(r0 + 1) * CD + j] = a1;
    if (r0 + 2 < NN) g_H2[(r0 + 2) * CD + j] = a2;
    if (r0 + 3 < NN) g_H2[(r0 + 3) * CD + j] = a3;
}

// ---------- agg2 (CSR gather) + self + bias + log_softmax, fused -------------
// 10 threads per node (4 feats each), 32 nodes per 320-thread block.
__global__ void k_agg2(const float* __restrict__ b2, float* __restrict__ out) {
    __shared__ float sp[32 * 10];
    __shared__ float sm[32];
    __shared__ float sl[32];

    int tid = threadIdx.x;
    int nl = tid / 10;           // node local 0..31
    int j  = tid % 10;           // feature quad
    int v  = blockIdx.x * 32 + nl;
    bool act = (v < NN);
    int c4 = j * 4;

    float a0 = 0.f, a1 = 0.f, a2 = 0.f, a3 = 0.f;
    if (act) {
        int e   = g_rowptr[v];
        int end = g_rowptr[v + 1];
        int src = 0; float nrm = 0.f;
        if (e < end) {
            int eid = g_csr[e];
            src = g_src[eid]; nrm = g_norm[eid];
        }
        while (e < end) {
            int src_c = src; float nrm_c = nrm;
            int e2 = e + 1;
            if (e2 < end) {
                int eid2 = g_csr[e2];
                src = g_src[eid2]; nrm = g_norm[eid2];
            }
            float4 h = *(const float4*)&g_H2[src_c * CD + c4];
            a0 += h.x * nrm_c; a1 += h.y * nrm_c;
            a2 += h.z * nrm_c; a3 += h.w * nrm_c;
            e = e2;
        }
        float di = g_deg[v];
        float sn = di * di;
        float4 hs = *(const float4*)&g_H2[v * CD + c4];
        float4 bb = *(const float4*)&b2[c4];
        a0 += hs.x * sn + bb.x;
        a1 += hs.y * sn + bb.y;
        a2 += hs.z * sn + bb.z;
        a3 += hs.w * sn + bb.w;
    }

    // partial max
    float pm = fmaxf(fmaxf(a0, a1), fmaxf(a2, a3));
    sp[nl * 10 + j] = act ? pm : -FLT_MAX;
    __syncthreads();
    if (j == 0) {
        float m = sp[nl * 10];
        #pragma unroll
        for (int t = 1; t < 10; t++) m = fmaxf(m, sp[nl * 10 + t]);
        sm[nl] = m;
    }
    __syncthreads();
    float m = sm[nl];
    float ps = act ? (__expf(a0 - m) + __expf(a1 - m) + __expf(a2 - m) + __expf(a3 - m)) : 0.f;
    sp[nl * 10 + j] = ps;
    __syncthreads();
    if (j == 0) {
        float s = 0.f;
        #pragma unroll
        for (int t = 0; t < 10; t++) s += sp[nl * 10 + t];
        sl[nl] = m + __logf(s);
    }
    __syncthreads();
    if (act) {
        float ls = sl[nl];
        int base = v * CD + c4;
        out[base + 0] = a0 - ls;
        out[base + 1] = a1 - ls;
        out[base + 2] = a2 - ls;
        out[base + 3] = a3 - ls;
    }
}

extern "C" void kernel_launch(void* const* d_in, const int* in_sizes, int n_in,
                              void* d_out, int out_size) {
    const float* x   = (const float*)d_in[0];
    const void*  ei  = d_in[1];
    const float* ea  = (const float*)d_in[2];
    const float* W1  = (const float*)d_in[3];
    const float* b1  = (const float*)d_in[4];
    const float* W2  = (const float*)d_in[5];
    const float* b2  = (const float*)d_in[6];
    float*       out = (float*)d_out;

    k_detect <<<1, 256>>>(ei);
    k_extract<<<(EE + 255) / 256, 256>>>(ei);
    k_init   <<<(NN + 255) / 256, 256>>>();
    k_count  <<<(EE + 255) / 256, 256>>>(ea);
    k_dinv   <<<(NN + 255) / 256, 256>>>();
    k_norm   <<<(EE + 255) / 256, 256>>>(ea);
    k_scan1  <<<NB, 1024>>>();
    k_scan2  <<<1, 128>>>();
    k_scan3  <<<NB, 1024>>>();
    k_fill   <<<(EE + 255) / 256, 256>>>();
    k_gemm1  <<<(NN + 255) / 256, 256>>>(x, W1);
    k_agg1   <<<(NN + 15) / 16, 256>>>(b1);
    k_gemm2  <<<(NN + 31) / 32, 320>>>(W2);
    k_agg2   <<<(NN + 31) / 32, 320>>>(b2, out);
}

// round 9
// speedup vs baseline: 1.7983x; 1.1737x over previous
#include <cuda_runtime.h>
#include <cuda_bf16.h>
#include <math.h>
#include <float.h>

#define NN 100000
#define EE 1600000
#define FIN 256
#define HD 64
#define CD 40
#define NB 98                 // ceil(NN/1024) scan blocks
#define GB1 391               // gemm1 blocks: ceil(NN/256)
#define EB1 1563              // extract blocks: ceil(EE/1024)

// ---- scratch ----------------------------------------------------------------
__device__ __align__(16) float g_deg[NN];         // deg -> dinv in place
__device__ __align__(16) float g_H1[NN * HD];     // x@W1
__device__ __align__(16) float g_H1b[NN * HD];    // relu(agg1)
__device__ __align__(16) float g_H2[NN * CD];     // h1b@W2
__device__ int   g_src[EE];
__device__ int   g_dst[EE];
__device__ int   g_cnt[NN];
__device__ int   g_cur[NN];
__device__ int   g_rowptr[NN + 1];
__device__ int   g_bsum[128];
__device__ int   g_csr_src[EE];                    // src in CSR (dst-sorted) order
__device__ __align__(16) float g_csr_norm[EE];     // norm in CSR order

// ---------- K0: init cnt/deg -------------------------------------------------
__global__ void k_init() {
    int i = blockIdx.x * blockDim.x + threadIdx.x;
    if (i < NN) { g_deg[i] = 1.0f; g_cnt[i] = 0; }
}

// ---------- K1 (fat): gemm1 | extract+count ----------------------------------
__global__ void k_fat1(const float* __restrict__ x, const float* __restrict__ W1,
                       const void* __restrict__ ei, const float* __restrict__ w) {
    __shared__ float sW[16 * 64];
    __shared__ float sxT[16 * 264];

    int tid = threadIdx.x;

    if (blockIdx.x < GB1) {
        // ---------------- GEMM1 tile: 256 rows, 8x8 reg blocking -------------
        int rowbase = blockIdx.x * 256;
        int tx = tid & 7;
        int ty = tid >> 3;

        float acc[8][8];
        #pragma unroll
        for (int i = 0; i < 8; i++)
            #pragma unroll
            for (int j = 0; j < 8; j++) acc[i][j] = 0.f;

        for (int kc = 0; kc < 16; kc++) {
            __syncthreads();
            #pragma unroll
            for (int i = tid; i < 1024; i += 256)
                sW[i] = W1[(kc * 16 + (i >> 6)) * 64 + (i & 63)];
            #pragma unroll
            for (int i = tid; i < 1024; i += 256) {
                int r = i >> 2, kq = (i & 3) * 4;
                int row = rowbase + r;
                float4 v = (row < NN) ? *(const float4*)&x[row * FIN + kc * 16 + kq]
                                      : make_float4(0.f, 0.f, 0.f, 0.f);
                sxT[(kq + 0) * 264 + r] = v.x;
                sxT[(kq + 1) * 264 + r] = v.y;
                sxT[(kq + 2) * 264 + r] = v.z;
                sxT[(kq + 3) * 264 + r] = v.w;
            }
            __syncthreads();
            #pragma unroll
            for (int k = 0; k < 16; k++) {
                float xr[8], wn[8];
                *(float4*)&xr[0] = *(const float4*)&sxT[k * 264 + ty * 8];
                *(float4*)&xr[4] = *(const float4*)&sxT[k * 264 + ty * 8 + 4];
                *(float4*)&wn[0] = *(const float4*)&sW[k * 64 + tx * 8];
                *(float4*)&wn[4] = *(const float4*)&sW[k * 64 + tx * 8 + 4];
                #pragma unroll
                for (int i = 0; i < 8; i++)
                    #pragma unroll
                    for (int j = 0; j < 8; j++)
                        acc[i][j] += xr[i] * wn[j];
            }
        }
        #pragma unroll
        for (int i = 0; i < 8; i++) {
            int row = rowbase + ty * 8 + i;
            if (row < NN) {
                *(float4*)&g_H1[row * HD + tx * 8]     = make_float4(acc[i][0], acc[i][1], acc[i][2], acc[i][3]);
                *(float4*)&g_H1[row * HD + tx * 8 + 4] = make_float4(acc[i][4], acc[i][5], acc[i][6], acc[i][7]);
            }
        }
    } else {
        // ---------------- extract + count: 1024 edges per block --------------
        int base = (blockIdx.x - GB1) * 1024;
        const long long* p64 = (const long long*)ei;
        const int*       p32 = (const int*)ei;

        // per-block dtype detection: 256 samples from this block's own range
        long long v = p64[base + tid];            // base+255 <= 1599743 < EE: in-bounds for both dtypes
        int bad = (v < 0 || v >= NN) ? 1 : 0;
        int is64 = !__syncthreads_or(bad);

        #pragma unroll
        for (int i = 0; i < 4; i++) {
            int e = base + i * 256 + tid;
            if (e < EE) {
                int s, d;
                if (is64) { s = (int)p64[e]; d = (int)p64[EE + e]; }
                else      { s = p32[e];      d = p32[EE + e]; }
                g_src[e] = s; g_dst[e] = d;
                atomicAdd(&g_cnt[d], 1);
                atomicAdd(&g_deg[d], w[e]);
            }
        }
    }
}

// ---------- K2 (fat): scan1 | dinv + cur=0 -----------------------------------
__global__ void k_fat2() {
    int b = blockIdx.x, t = threadIdx.x;
    if (b < NB) {
        __shared__ int s[1024];
        int i = b * 1024 + t;
        int v = (i < NN) ? g_cnt[i] : 0;
        s[t] = v; __syncthreads();
        for (int off = 1; off < 1024; off <<= 1) {
            int add = (t >= off) ? s[t - off] : 0;
            __syncthreads();
            s[t] += add;
            __syncthreads();
        }
        if (i < NN) g_rowptr[i + 1] = s[t];
        if (t == 1023) g_bsum[b] = s[t];
    } else {
        int i = (b - NB) * 1024 + t;
        if (i < NN) {
            float d = g_deg[i];
            g_deg[i] = (d > 0.f) ? rsqrtf(d) : 0.f;
            g_cur[i] = 0;
        }
    }
}

// ---------- K3: scan of block sums -------------------------------------------
__global__ void k_scan2() {
    __shared__ int s[128];
    int t = threadIdx.x;
    int v = (t < NB) ? g_bsum[t] : 0;
    s[t] = v; __syncthreads();
    for (int off = 1; off < 128; off <<= 1) {
        int add = (t >= off) ? s[t - off] : 0;
        __syncthreads();
        s[t] += add;
        __syncthreads();
    }
    if (t < NB) g_bsum[t] = s[t];
}

// ---------- K4: add block offsets --------------------------------------------
__global__ void k_scan3() {
    int b = blockIdx.x, t = threadIdx.x;
    int i = b * 1024 + t;
    if (b > 0 && i < NN) g_rowptr[i + 1] += g_bsum[b - 1];
    if (b == 0 && t == 0) g_rowptr[0] = 0;
}

// ---------- K5: fill CSR (+ norm inline) -------------------------------------
__global__ void k_fill(const float* __restrict__ w) {
    int e = blockIdx.x * blockDim.x + threadIdx.x;
    if (e < EE) {
        int s = g_src[e];
        int d = g_dst[e];
        float nrm = g_deg[s] * w[e] * g_deg[d];
        int p = atomicAdd(&g_cur[d], 1);
        int pos = g_rowptr[d] + p;
        g_csr_src[pos]  = s;
        g_csr_norm[pos] = nrm;
    }
}

// ---------- K6: agg1 (CSR gather) + self + bias + relu -----------------------
// 16 threads per node; each handles 4 features; unroll 2 for MLP.
__global__ void k_agg1(const float* __restrict__ b1) {
    int tid = threadIdx.x;
    int v  = blockIdx.x * 16 + (tid >> 4);
    if (v >= NN) return;
    int c4 = (tid & 15) * 4;

    int e   = g_rowptr[v];
    int end = g_rowptr[v + 1];
    float4 acc = make_float4(0.f, 0.f, 0.f, 0.f);

    for (; e + 2 <= end; e += 2) {
        int   s0 = g_csr_src[e],     s1 = g_csr_src[e + 1];
        float n0 = g_csr_norm[e],    n1 = g_csr_norm[e + 1];
        float4 h0 = *(const float4*)&g_H1[s0 * HD + c4];
        float4 h1 = *(const float4*)&g_H1[s1 * HD + c4];
        acc.x += h0.x * n0 + h1.x * n1;
        acc.y += h0.y * n0 + h1.y * n1;
        acc.z += h0.z * n0 + h1.z * n1;
        acc.w += h0.w * n0 + h1.w * n1;
    }
    if (e < end) {
        int   s0 = g_csr_src[e];
        float n0 = g_csr_norm[e];
        float4 h0 = *(const float4*)&g_H1[s0 * HD + c4];
        acc.x += h0.x * n0; acc.y += h0.y * n0;
        acc.z += h0.z * n0; acc.w += h0.w * n0;
    }

    float di = g_deg[v];
    float sn = di * di;
    float4 hs = *(const float4*)&g_H1[v * HD + c4];
    float4 bb = *(const float4*)&b1[c4];
    float4 o;
    o.x = fmaxf(acc.x + hs.x * sn + bb.x, 0.f);
    o.y = fmaxf(acc.y + hs.y * sn + bb.y, 0.f);
    o.z = fmaxf(acc.z + hs.z * sn + bb.z, 0.f);
    o.w = fmaxf(acc.w + hs.w * sn + bb.w, 0.f);
    *(float4*)&g_H1b[v * HD + c4] = o;
}

// ---------- K7: GEMM2 H2 = H1b @ W2 ------------------------------------------
__global__ void k_gemm2(const float* __restrict__ W2) {
    __shared__ float sW2[64 * 40];
    __shared__ float sx[32 * 64];

    int tid = threadIdx.x;
    int rowbase = blockIdx.x * 32;

    for (int idx = tid; idx < 64 * 40; idx += 320)
        sW2[idx] = W2[idx];
    for (int idx = tid; idx < 32 * 64; idx += 320) {
        int r = idx >> 6, k = idx & 63;
        int row = rowbase + r;
        sx[idx] = (row < NN) ? g_H1b[row * HD + k] : 0.f;
    }
    __syncthreads();

    int j  = tid % 40;
    int rg = tid / 40;
    float a0 = 0.f, a1 = 0.f, a2 = 0.f, a3 = 0.f;
    #pragma unroll
    for (int k = 0; k < 64; k++) {
        float w = sW2[k * 40 + j];
        a0 += sx[(rg * 4 + 0) * 64 + k] * w;
        a1 += sx[(rg * 4 + 1) * 64 + k] * w;
        a2 += sx[(rg * 4 + 2) * 64 + k] * w;
        a3 += sx[(rg * 4 + 3) * 64 + k] * w;
    }
    int r0 = rowbase + rg * 4;
    if (r0 + 0 < NN) g_H2[(r0 + 0) * CD + j] = a0;
    if (r0 + 1 < NN) g_H2[(r0 + 1) * CD + j] = a1;
    if (r0 + 2 < NN) g_H2[(r0 + 2) * CD + j] = a2;
    if (r0 + 3 < NN) g_H2[(r0 + 3) * CD + j] = a3;
}

// ---------- K8: agg2 (CSR gather) + self + bias + log_softmax ----------------
__global__ void k_agg2(const float* __restrict__ b2, float* __restrict__ out) {
    __shared__ float sp[32 * 10];
    __shared__ float sm[32];
    __shared__ float sl[32];

    int tid = threadIdx.x;
    int nl = tid / 10;
    int j  = tid % 10;
    int v  = blockIdx.x * 32 + nl;
    bool act = (v < NN);
    int c4 = j * 4;

    float a0 = 0.f, a1 = 0.f, a2 = 0.f, a3 = 0.f;
    if (act) {
        int e   = g_rowptr[v];
        int end = g_rowptr[v + 1];
        for (; e + 2 <= end; e += 2) {
            int   s0 = g_csr_src[e],  s1 = g_csr_src[e + 1];
            float n0 = g_csr_norm[e], n1 = g_csr_norm[e + 1];
            float4 h0 = *(const float4*)&g_H2[s0 * CD + c4];
            float4 h1 = *(const float4*)&g_H2[s1 * CD + c4];
            a0 += h0.x * n0 + h1.x * n1;
            a1 += h0.y * n0 + h1.y * n1;
            a2 += h0.z * n0 + h1.z * n1;
            a3 += h0.w * n0 + h1.w * n1;
        }
        if (e < end) {
            int   s0 = g_csr_src[e];
            float n0 = g_csr_norm[e];
            float4 h0 = *(const float4*)&g_H2[s0 * CD + c4];
            a0 += h0.x * n0; a1 += h0.y * n0;
            a2 += h0.z * n0; a3 += h0.w * n0;
        }
        float di = g_deg[v];
        float sn = di * di;
        float4 hs = *(const float4*)&g_H2[v * CD + c4];
        float4 bb = *(const float4*)&b2[c4];
        a0 += hs.x * sn + bb.x;
        a1 += hs.y * sn + bb.y;
        a2 += hs.z * sn + bb.z;
        a3 += hs.w * sn + bb.w;
    }

    float pm = fmaxf(fmaxf(a0, a1), fmaxf(a2, a3));
    sp[nl * 10 + j] = act ? pm : -FLT_MAX;
    __syncthreads();
    if (j == 0) {
        float m = sp[nl * 10];
        #pragma unroll
        for (int t = 1; t < 10; t++) m = fmaxf(m, sp[nl * 10 + t]);
        sm[nl] = m;
    }
    __syncthreads();
    float m = sm[nl];
    float ps = act ? (__expf(a0 - m) + __expf(a1 - m) + __expf(a2 - m) + __expf(a3 - m)) : 0.f;
    sp[nl * 10 + j] = ps;
    __syncthreads();
    if (j == 0) {
        float s = 0.f;
        #pragma unroll
        for (int t = 0; t < 10; t++) s += sp[nl * 10 + t];
        sl[nl] = m + __logf(s);
    }
    __syncthreads();
    if (act) {
        float ls = sl[nl];
        int base = v * CD + c4;
        out[base + 0] = a0 - ls;
        out[base + 1] = a1 - ls;
        out[base + 2] = a2 - ls;
        out[base + 3] = a3 - ls;
    }
}

extern "C" void kernel_launch(void* const* d_in, const int* in_sizes, int n_in,
                              void* d_out, int out_size) {
    const float* x   = (const float*)d_in[0];
    const void*  ei  = d_in[1];
    const float* ea  = (const float*)d_in[2];
    const float* W1  = (const float*)d_in[3];
    const float* b1  = (const float*)d_in[4];
    const float* W2  = (const float*)d_in[5];
    const float* b2  = (const float*)d_in[6];
    float*       out = (float*)d_out;

    k_init <<<(NN + 255) / 256, 256>>>();
    k_fat1 <<<GB1 + EB1, 256>>>(x, W1, ei, ea);
    k_fat2 <<<2 * NB, 1024>>>();
    k_scan2<<<1, 128>>>();
    k_scan3<<<NB, 1024>>>();
    k_fill <<<(EE + 255) / 256, 256>>>(ea);
    k_agg1 <<<(NN + 15) / 16, 256>>>(b1);
    k_gemm2<<<(NN + 31) / 32, 320>>>(W2);
    k_agg2 <<<(NN + 31) / 32, 320>>>(b2, out);
}